// round 8
// baseline (speedup 1.0000x reference)
#include <cuda_runtime.h>

// ---------------------------------------------------------------------------
// B=16, H=W=1024, ROUTE=(512,256) -> ph=2, pw=4, L=8, NPATCH=128
// scale i: W_i=1024>>i, kh=512>>i, kw=256>>i
// out: [0]=loss, [1..16M]=out_img, [16M+1..32M]=lab_img
//
// Fused persistent design: one kernel drains 5504 reduce tasks via a global
// ticket, finalizes per-patch argmin as counts complete, and writer blocks
// spin on per-image ready flags -> read & write DRAM streams overlap.
// ---------------------------------------------------------------------------

#define NPATCH 128
#define IMG0   16777216
#define NTASK  5504
#define NWBLK  16384
#define PADV   (0.2f / 200.0f)

__device__ double g_pA[NPATCH * 43];
__device__ double g_pC[NPATCH * 43];
__device__ double g_pQ[NPATCH * 43];
__device__ double g_Qsel[NPATCH];
__device__ int    g_mask[NPATCH];
__device__ int    g_cnt[NPATCH];
__device__ int    g_imgReady[16];
__device__ int    g_ticket;

// ---------------------------------------------------------------------------
__global__ void k_zero() {
    int t = threadIdx.x;
    if (t < NPATCH) g_cnt[t] = 0;
    if (t < 16)     g_imgReady[t] = 0;
    if (t == 0)     g_ticket = 0;
}

// ---------------------------------------------------------------------------
#define WARP_DRED(v) { v += __shfl_down_sync(0xffffffffu, v, 16); \
                       v += __shfl_down_sync(0xffffffffu, v, 8);  \
                       v += __shfl_down_sync(0xffffffffu, v, 4);  \
                       v += __shfl_down_sync(0xffffffffu, v, 2);  \
                       v += __shfl_down_sync(0xffffffffu, v, 1); }

// One reduce task (one 4096-element-per-iter slice of one patch at one scale).
__device__ __forceinline__ void reduce_task(
    int tk, int tid,
    const float* __restrict__ p0, const float* __restrict__ p1,
    const float* __restrict__ p2, const float* __restrict__ p3,
    const float* __restrict__ g0, const float* __restrict__ g1,
    const float* __restrict__ g2, const float* __restrict__ g3,
    float* fA, float* fC, float* fQ)
{
    int scale, patch, local, slice;
    if (tk < 1024)      { scale = 1; patch = tk >> 3;          local = 32 + (tk & 7); slice = tk & 7; }
    else if (tk < 1280) { scale = 2; patch = (tk - 1024) >> 1; local = 40 + (tk & 1); slice = tk & 1; }
    else if (tk < 1408) { scale = 3; patch = tk - 1280;        local = 42;            slice = 0;      }
    else                { int r = tk - 1408; scale = 0; patch = r >> 5; local = r & 31; slice = r & 31; }

    const int kwS_t[4] = {8, 7, 6, 5};
    const int wS_t[4]  = {10, 9, 8, 7};
    int kwS = kwS_t[scale];
    int wS  = wS_t[scale];

    const float* pre = (scale == 0) ? p0 : (scale == 1) ? p1 : (scale == 2) ? p2 : p3;
    const float* gt  = (scale == 0) ? g0 : (scale == 1) ? g1 : (scale == 2) ? g2 : g3;

    int b  = patch >> 3;
    int pr = (patch >> 2) & 1;
    int pc = patch & 3;

    int qpwS = kwS - 2;
    int row  = tid >> qpwS;
    int col4 = (tid & ((1 << qpwS) - 1)) << 2;
    int rpi  = 256 >> qpwS;
    int rpb  = (scale == 3) ? (rpi << 1) : (rpi << 2);

    int kh  = 512 >> scale;
    int gy  = pr * kh + slice * rpb + row;
    int gx  = (pc << kwS) + col4;
    int idx = (b << (2 * wS)) + (gy << wS) + gx;

    float4 P[4], G[4];
    int nit;
    if (scale == 0) {                               // caching: L2-resident for writers
        P[0] = *(const float4*)(pre + idx);
        G[0] = *(const float4*)(gt  + idx);
        P[1] = *(const float4*)(pre + idx + 4096);
        G[1] = *(const float4*)(gt  + idx + 4096);
        P[2] = *(const float4*)(pre + idx + 8192);
        G[2] = *(const float4*)(gt  + idx + 8192);
        P[3] = *(const float4*)(pre + idx + 12288);
        G[3] = *(const float4*)(gt  + idx + 12288);
        nit = 4;
    } else if (scale != 3) {
        P[0] = __ldcs((const float4*)(pre + idx));
        G[0] = __ldcs((const float4*)(gt  + idx));
        P[1] = __ldcs((const float4*)(pre + idx + 4096));
        G[1] = __ldcs((const float4*)(gt  + idx + 4096));
        P[2] = __ldcs((const float4*)(pre + idx + 8192));
        G[2] = __ldcs((const float4*)(gt  + idx + 8192));
        P[3] = __ldcs((const float4*)(pre + idx + 12288));
        G[3] = __ldcs((const float4*)(gt  + idx + 12288));
        nit = 4;
    } else {
        P[0] = __ldcs((const float4*)(pre + idx));
        G[0] = __ldcs((const float4*)(gt  + idx));
        P[1] = __ldcs((const float4*)(pre + idx + 4096));
        G[1] = __ldcs((const float4*)(gt  + idx + 4096));
        nit = 2;
    }

    float sg = 0.f, spp = 0.f, cnt = 0.f, ssq = 0.f;
    #define ACC(pp, gg) { float e = fmaf((gg), -200.0f, (pp));       \
                          ssq = fmaf(e, e, ssq); sg += (gg);         \
                          if (e < 0.0f) { cnt += 1.0f; spp += (pp); } }
    #pragma unroll
    for (int it = 0; it < 4; ++it) {
        if (it < nit) {
            ACC(P[it].x, G[it].x) ACC(P[it].y, G[it].y)
            ACC(P[it].z, G[it].z) ACC(P[it].w, G[it].w)
        }
    }
    #undef ACC

    fA[tid] = fmaf(sg, 200.0f, -spp);               // sabs = 200*Sum(g)-Sum_pos(p)
    fC[tid] = cnt;
    fQ[tid] = ssq;
    __syncthreads();

    if (tid < 32) {
        double dA = 0.0, dC = 0.0, dQ = 0.0;
        #pragma unroll
        for (int j = 0; j < 8; ++j) {
            int k = tid + (j << 5);
            dA += (double)fA[k];
            dC += (double)fC[k];
            dQ += (double)fQ[k];
        }
        WARP_DRED(dA) WARP_DRED(dC) WARP_DRED(dQ)

        int fin = 0;
        int pb = patch * 43;
        if (tid == 0) {
            __stcg(&g_pA[pb + local], dA);
            __stcg(&g_pC[pb + local], dC);
            __stcg(&g_pQ[pb + local], dQ);
            __threadfence();
            int old = atomicAdd(&g_cnt[patch], 1);
            fin = (old == 42);
        }
        fin = __shfl_sync(0xffffffffu, fin, 0);

        if (fin) {                                   // finalize patch: argmin
            __threadfence();
            int lane = tid;
            double A[4], C[4], Q[4];
            // scale0: 32 slices
            double a = __ldcg(&g_pA[pb + lane]);
            double c = __ldcg(&g_pC[pb + lane]);
            double q = __ldcg(&g_pQ[pb + lane]);
            WARP_DRED(a) WARP_DRED(c) WARP_DRED(q)
            A[0] = a; C[0] = c; Q[0] = q;
            // scale1: 8 slices
            a = (lane < 8) ? __ldcg(&g_pA[pb + 32 + lane]) : 0.0;
            c = (lane < 8) ? __ldcg(&g_pC[pb + 32 + lane]) : 0.0;
            q = (lane < 8) ? __ldcg(&g_pQ[pb + 32 + lane]) : 0.0;
            WARP_DRED(a) WARP_DRED(c) WARP_DRED(q)
            A[1] = a; C[1] = c; Q[1] = q;
            // scale2: 2 slices
            a = (lane < 2) ? __ldcg(&g_pA[pb + 40 + lane]) : 0.0;
            c = (lane < 2) ? __ldcg(&g_pC[pb + 40 + lane]) : 0.0;
            q = (lane < 2) ? __ldcg(&g_pQ[pb + 40 + lane]) : 0.0;
            WARP_DRED(a) WARP_DRED(c) WARP_DRED(q)
            A[2] = a; C[2] = c; Q[2] = q;
            // scale3: 1 slice
            A[3] = (lane == 0) ? __ldcg(&g_pA[pb + 42]) : 0.0;
            C[3] = (lane == 0) ? __ldcg(&g_pC[pb + 42]) : 0.0;
            Q[3] = (lane == 0) ? __ldcg(&g_pQ[pb + 42]) : 0.0;

            if (lane == 0) {
                double best = 1e300;
                int mi = 0;
                #pragma unroll
                for (int i = 0; i < 4; ++i) {
                    double e = A[i] / (C[i] + (double)0.1f);
                    if (e < best) { best = e; mi = i; }   // first-min argmin
                }
                __stcg(&g_mask[patch], mi);
                __stcg(&g_Qsel[patch], Q[mi]);
                __threadfence();
                atomicAdd(&g_imgReady[patch >> 3], 1);
            }
        }
    }
    __syncthreads();
}

// ---------------------------------------------------------------------------
// Aligned-quad compose using smem-cached masks (patchBase = b<<3, sm[16]).
__device__ __forceinline__ void quad_val_s(
    int P0, const int* sm, int patchBase,
    const float* __restrict__ p0, const float* __restrict__ p1,
    const float* __restrict__ p2, const float* __restrict__ p3,
    const float* __restrict__ g0, const float* __restrict__ g1,
    const float* __restrict__ g2, const float* __restrict__ g3,
    float4& vo, float4& vl)
{
    int b  = P0 >> 20;
    int r  = P0 & 1048575;
    int Y  = r >> 10;
    int X  = r & 1023;
    int pr = Y >> 9;
    int pc = X >> 8;
    int mi = sm[((b << 3) | (pr << 2) | pc) - patchBase];
    int kh = 512 >> mi;
    int kw = 256 >> mi;
    int iy = (Y & 511) - ((512 - kh) >> 1);
    int ix = (X & 255) - ((256 - kw) >> 1);
    vo = make_float4(PADV, PADV, PADV, PADV);
    vl = vo;
    if ((unsigned)iy < (unsigned)kh && (unsigned)ix < (unsigned)kw) {
        int ws  = 10 - mi;
        int idx = (b << (2 * ws)) + ((pr * kh + iy) << ws)
                + (pc << (8 - mi)) + ix;
        const float* pp = (mi == 0) ? p0 : (mi == 1) ? p1 : (mi == 2) ? p2 : p3;
        const float* gg = (mi == 0) ? g0 : (mi == 1) ? g1 : (mi == 2) ? g2 : g3;
        float4 p = *(const float4*)(pp + idx);
        float4 q = *(const float4*)(gg + idx);
        vo = make_float4(p.x / 200.0f, p.y / 200.0f, p.z / 200.0f, p.w / 200.0f);
        vl = make_float4((q.x * 200.0f) / 200.0f, (q.y * 200.0f) / 200.0f,
                         (q.z * 200.0f) / 200.0f, (q.w * 200.0f) / 200.0f);
    }
}

__device__ __forceinline__ void pixel_val_s(
    int P, const int* sm, int patchBase,
    const float* __restrict__ p0, const float* __restrict__ p1,
    const float* __restrict__ p2, const float* __restrict__ p3,
    const float* __restrict__ g0, const float* __restrict__ g1,
    const float* __restrict__ g2, const float* __restrict__ g3,
    float& o, float& l)
{
    int b  = P >> 20;
    int r  = P & 1048575;
    int Y  = r >> 10;
    int X  = r & 1023;
    int pr = Y >> 9;
    int pc = X >> 8;
    int mi = sm[((b << 3) | (pr << 2) | pc) - patchBase];
    int kh = 512 >> mi;
    int kw = 256 >> mi;
    int iy = (Y & 511) - ((512 - kh) >> 1);
    int ix = (X & 255) - ((256 - kw) >> 1);
    o = PADV; l = PADV;
    if ((unsigned)iy < (unsigned)kh && (unsigned)ix < (unsigned)kw) {
        int ws  = 10 - mi;
        int idx = (b << (2 * ws)) + ((pr * kh + iy) << ws)
                + (pc << (8 - mi)) + ix;
        const float* pp = (mi == 0) ? p0 : (mi == 1) ? p1 : (mi == 2) ? p2 : p3;
        const float* gg = (mi == 0) ? g0 : (mi == 1) ? g1 : (mi == 2) ? g2 : g3;
        o = pp[idx] / 200.0f;
        l = (gg[idx] * 200.0f) / 200.0f;
    }
}

// ---------------------------------------------------------------------------
__global__ void __launch_bounds__(256)
k_fused(const float* __restrict__ p0, const float* __restrict__ p1,
        const float* __restrict__ p2, const float* __restrict__ p3,
        const float* __restrict__ g0, const float* __restrict__ g1,
        const float* __restrict__ g2, const float* __restrict__ g3,
        float* __restrict__ out)
{
    __shared__ float fA[256], fC[256], fQ[256];
    __shared__ int   s_tk;
    __shared__ int   s_mask[16];
    __shared__ float s_pub[8][6];

    int tid = threadIdx.x;

    // ---- phase 1: drain reduce tickets (deadlock-free work pull) ----
    while (true) {
        if (tid == 0) s_tk = atomicAdd(&g_ticket, 1);
        __syncthreads();
        int tk = s_tk;
        __syncthreads();
        if (tk >= NTASK) break;
        reduce_task(tk, tid, p0, p1, p2, p3, g0, g1, g2, g3, fA, fC, fQ);
    }

    // ---- phase 2: write chunk (1024 px of out_img & lab_img) ----
    int w    = blockIdx.x;                        // 0..16383
    int base = w << 10;
    int b    = base >> 20;
    bool cross = ((w & 1023) == 1023) && (b < 15);

    if (tid == 0) {
        int spin = 64;
        while (atomicAdd(&g_imgReady[b], 0) < 8) { __nanosleep(spin); if (spin < 2048) spin <<= 1; }
        if (cross) {
            spin = 64;
            while (atomicAdd(&g_imgReady[b + 1], 0) < 8) { __nanosleep(spin); if (spin < 2048) spin <<= 1; }
        }
    }
    __syncthreads();
    __threadfence();
    if (tid < 16) {
        int pidx = (b << 3) + tid;
        s_mask[tid] = (pidx < NPATCH) ? __ldcg(&g_mask[pidx]) : 0;
    }
    __syncthreads();

    int pb8  = b << 3;
    int g    = w * 256 + tid;                     // quad id
    int P0   = g << 2;
    int lane = tid & 31;
    int wrp  = tid >> 5;

    float4 vo, vl;
    quad_val_s(P0, s_mask, pb8, p0, p1, p2, p3, g0, g1, g2, g3, vo, vl);

    if (lane == 0) {
        s_pub[wrp][0] = vo.x; s_pub[wrp][1] = vo.y; s_pub[wrp][2] = vo.z;
        s_pub[wrp][3] = vl.x; s_pub[wrp][4] = vl.y; s_pub[wrp][5] = vl.z;
    }
    __syncthreads();

    float nox = __shfl_down_sync(0xffffffffu, vo.x, 1);
    float noy = __shfl_down_sync(0xffffffffu, vo.y, 1);
    float noz = __shfl_down_sync(0xffffffffu, vo.z, 1);
    float nlx = __shfl_down_sync(0xffffffffu, vl.x, 1);
    float nly = __shfl_down_sync(0xffffffffu, vl.y, 1);
    float nlz = __shfl_down_sync(0xffffffffu, vl.z, 1);

    bool lastGlobal = (g == 4194303);

    if (lane == 31) {
        if (tid != 255) {
            nox = s_pub[wrp + 1][0]; noy = s_pub[wrp + 1][1]; noz = s_pub[wrp + 1][2];
            nlx = s_pub[wrp + 1][3]; nly = s_pub[wrp + 1][4]; nlz = s_pub[wrp + 1][5];
        } else if (!lastGlobal) {
            int Pn = base + 1024;                 // next block's first 3 pixels
            pixel_val_s(Pn,     s_mask, pb8, p0, p1, p2, p3, g0, g1, g2, g3, nox, nlx);
            pixel_val_s(Pn + 1, s_mask, pb8, p0, p1, p2, p3, g0, g1, g2, g3, noy, nly);
            pixel_val_s(Pn + 2, s_mask, pb8, p0, p1, p2, p3, g0, g1, g2, g3, noz, nlz);
        }
    }

    if (!lastGlobal) {
        float* ob = out + 1;
        float* lb = out + 1 + IMG0;
        int k = P0 + 3;                           // 16B aligned
        __stcs((float4*)(ob + k), make_float4(vo.w, nox, noy, noz));
        __stcs((float4*)(lb + k), make_float4(vl.w, nlx, nly, nlz));
    }
    // pixels 0,1,2 and 16777215 of both arrays handled in k_loss
}

// ---------------------------------------------------------------------------
// Global pixel_val (masks final here).
__device__ __forceinline__ void pixel_val_g(
    int P,
    const float* __restrict__ p0, const float* __restrict__ p1,
    const float* __restrict__ p2, const float* __restrict__ p3,
    const float* __restrict__ g0, const float* __restrict__ g1,
    const float* __restrict__ g2, const float* __restrict__ g3,
    float& o, float& l)
{
    int b  = P >> 20;
    int r  = P & 1048575;
    int Y  = r >> 10;
    int X  = r & 1023;
    int pr = Y >> 9;
    int pc = X >> 8;
    int mi = g_mask[(b << 3) | (pr << 2) | pc];
    int kh = 512 >> mi;
    int kw = 256 >> mi;
    int iy = (Y & 511) - ((512 - kh) >> 1);
    int ix = (X & 255) - ((256 - kw) >> 1);
    o = PADV; l = PADV;
    if ((unsigned)iy < (unsigned)kh && (unsigned)ix < (unsigned)kw) {
        int ws  = 10 - mi;
        int idx = (b << (2 * ws)) + ((pr * kh + iy) << ws)
                + (pc << (8 - mi)) + ix;
        const float* pp = (mi == 0) ? p0 : (mi == 1) ? p1 : (mi == 2) ? p2 : p3;
        const float* gg = (mi == 0) ? g0 : (mi == 1) ? g1 : (mi == 2) ? g2 : g3;
        o = pp[idx] / 200.0f;
        l = (gg[idx] * 200.0f) / 200.0f;
    }
}

__global__ void k_loss(const float* __restrict__ p0, const float* __restrict__ p1,
                       const float* __restrict__ p2, const float* __restrict__ p3,
                       const float* __restrict__ g0, const float* __restrict__ g1,
                       const float* __restrict__ g2, const float* __restrict__ g3,
                       float* __restrict__ out)
{
    int t = threadIdx.x;
    if (t == 0) {
        double num[4] = {0.0, 0.0, 0.0, 0.0};
        int    cnt[4] = {0, 0, 0, 0};
        for (int p = 0; p < NPATCH; ++p) {        // fixed order: deterministic
            int mi = g_mask[p];
            num[mi] += g_Qsel[p];
            cnt[mi] += 1;
        }
        const double w[4]  = {0.5, 0.25, 0.125, 0.0625};
        const double pe[4] = {131072.0, 32768.0, 8192.0, 2048.0};
        double loss = 0.0;
        #pragma unroll
        for (int i = 0; i < 4; ++i)
            loss += w[i] * (num[i] / ((double)cnt[i] * pe[i] + (double)0.01f));
        out[0] = (float)loss;
    } else if (t < 5) {
        const int Ps[4] = {0, 1, 2, 16777215};
        int P = Ps[t - 1];
        float o, l;
        pixel_val_g(P, p0, p1, p2, p3, g0, g1, g2, g3, o, l);
        out[1 + P] = o;
        out[1 + IMG0 + P] = l;
    }
}

// ---------------------------------------------------------------------------
extern "C" void kernel_launch(void* const* d_in, const int* in_sizes, int n_in,
                              void* d_out, int out_size)
{
    const float *pre[4], *gt[4];
    if (n_in >= 8 && in_sizes[1] == in_sizes[0]) {        // interleaved
        for (int i = 0; i < 4; ++i) {
            pre[i] = (const float*)d_in[2 * i];
            gt [i] = (const float*)d_in[2 * i + 1];
        }
    } else {                                              // grouped
        for (int i = 0; i < 4; ++i) {
            pre[i] = (const float*)d_in[i];
            gt [i] = (const float*)d_in[4 + i];
        }
    }
    float* out = (float*)d_out;

    k_zero<<<1, 160>>>();
    k_fused<<<NWBLK, 256>>>(pre[0], pre[1], pre[2], pre[3],
                            gt[0], gt[1], gt[2], gt[3], out);
    k_loss<<<1, 32>>>(pre[0], pre[1], pre[2], pre[3],
                      gt[0], gt[1], gt[2], gt[3], out);
    (void)out_size;
}

// round 9
// speedup vs baseline: 1.0028x; 1.0028x over previous
#include <cuda_runtime.h>

// ---------------------------------------------------------------------------
// B=16, H=W=1024, ROUTE=(512,256) -> ph=2, pw=4, L=8, NPATCH=128
// scale i: W_i=1024>>i, kh=512>>i, kw=256>>i
// out: [0]=loss, [1..16M]=out_img, [16M+1..32M]=lab_img
//
// Fused help-first design: writer blocks for image b pull reduce tickets
// (image-major order) ONLY until image b is ready, then write. Read and
// write DRAM streams overlap; deadlock-free by construction.
// ---------------------------------------------------------------------------

#define NPATCH 128
#define IMG0   16777216
#define NTASK  5504          // 16 images x 8 patches x 43 slices
#define PADV   (0.2f / 200.0f)

__device__ double g_pA[NPATCH * 43];
__device__ double g_pC[NPATCH * 43];
__device__ double g_pQ[NPATCH * 43];
__device__ double g_Qsel[NPATCH];
__device__ int    g_mask[NPATCH];
__device__ int    g_cnt[NPATCH];
__device__ int    g_imgReady[16];
__device__ int    g_ticket;

// ---------------------------------------------------------------------------
__global__ void k_zero() {
    int t = threadIdx.x;
    if (t < NPATCH) g_cnt[t] = 0;
    if (t < 16)     g_imgReady[t] = 0;
    if (t == 0)     g_ticket = 0;
}

// ---------------------------------------------------------------------------
#define WARP_DRED(v) { v += __shfl_down_sync(0xffffffffu, v, 16); \
                       v += __shfl_down_sync(0xffffffffu, v, 8);  \
                       v += __shfl_down_sync(0xffffffffu, v, 4);  \
                       v += __shfl_down_sync(0xffffffffu, v, 2);  \
                       v += __shfl_down_sync(0xffffffffu, v, 1); }

// One reduce task: one 4096-element slice (2048 for scale3) of one patch.
// Ticket layout (image-major): tk = img*344 + patch_local*43 + s,
//   s in [0,32) scale0 | [32,40) scale1 | [40,42) scale2 | 42 scale3.
__device__ __forceinline__ void reduce_task(
    int tk, int tid,
    const float* __restrict__ p0, const float* __restrict__ p1,
    const float* __restrict__ p2, const float* __restrict__ p3,
    const float* __restrict__ g0, const float* __restrict__ g1,
    const float* __restrict__ g2, const float* __restrict__ g3,
    float* fA, float* fC, float* fQ)
{
    int img = tk / 344;
    int r   = tk - img * 344;
    int pl  = r / 43;
    int s   = r - pl * 43;
    int patch = (img << 3) + pl;

    int scale, slice;
    if      (s < 32) { scale = 0; slice = s;      }
    else if (s < 40) { scale = 1; slice = s - 32; }
    else if (s < 42) { scale = 2; slice = s - 40; }
    else             { scale = 3; slice = 0;      }
    int local = s;

    const int kwS_t[4] = {8, 7, 6, 5};
    const int wS_t[4]  = {10, 9, 8, 7};
    int kwS = kwS_t[scale];
    int wS  = wS_t[scale];

    const float* pre = (scale == 0) ? p0 : (scale == 1) ? p1 : (scale == 2) ? p2 : p3;
    const float* gt  = (scale == 0) ? g0 : (scale == 1) ? g1 : (scale == 2) ? g2 : g3;

    int b  = patch >> 3;
    int pr = (patch >> 2) & 1;
    int pc = patch & 3;

    int qpwS = kwS - 2;
    int row  = tid >> qpwS;
    int col4 = (tid & ((1 << qpwS) - 1)) << 2;
    int rpi  = 256 >> qpwS;                        // rows per iteration
    int rpb  = (scale == 3) ? (rpi << 1) : (rpi << 2);

    int kh  = 512 >> scale;
    int gy  = pr * kh + slice * rpb + row;
    int gx  = (pc << kwS) + col4;
    int idx = (b << (2 * wS)) + (gy << wS) + gx;

    float4 P[4], G[4];
    int nit;
    if (scale == 0) {                              // caching: L2-resident for writers
        P[0] = *(const float4*)(pre + idx);
        G[0] = *(const float4*)(gt  + idx);
        P[1] = *(const float4*)(pre + idx + 4096);
        G[1] = *(const float4*)(gt  + idx + 4096);
        P[2] = *(const float4*)(pre + idx + 8192);
        G[2] = *(const float4*)(gt  + idx + 8192);
        P[3] = *(const float4*)(pre + idx + 12288);
        G[3] = *(const float4*)(gt  + idx + 12288);
        nit = 4;
    } else if (scale != 3) {
        P[0] = __ldcs((const float4*)(pre + idx));
        G[0] = __ldcs((const float4*)(gt  + idx));
        P[1] = __ldcs((const float4*)(pre + idx + 4096));
        G[1] = __ldcs((const float4*)(gt  + idx + 4096));
        P[2] = __ldcs((const float4*)(pre + idx + 8192));
        G[2] = __ldcs((const float4*)(gt  + idx + 8192));
        P[3] = __ldcs((const float4*)(pre + idx + 12288));
        G[3] = __ldcs((const float4*)(gt  + idx + 12288));
        nit = 4;
    } else {
        P[0] = __ldcs((const float4*)(pre + idx));
        G[0] = __ldcs((const float4*)(gt  + idx));
        P[1] = __ldcs((const float4*)(pre + idx + 4096));
        G[1] = __ldcs((const float4*)(gt  + idx + 4096));
        nit = 2;
    }

    float sg = 0.f, spp = 0.f, cnt = 0.f, ssq = 0.f;
    #define ACC(pp, gg) { float e = fmaf((gg), -200.0f, (pp));       \
                          ssq = fmaf(e, e, ssq); sg += (gg);         \
                          if (e < 0.0f) { cnt += 1.0f; spp += (pp); } }
    #pragma unroll
    for (int it = 0; it < 4; ++it) {
        if (it < nit) {
            ACC(P[it].x, G[it].x) ACC(P[it].y, G[it].y)
            ACC(P[it].z, G[it].z) ACC(P[it].w, G[it].w)
        }
    }
    #undef ACC

    fA[tid] = fmaf(sg, 200.0f, -spp);              // sabs = 200*Sum(g)-Sum_pos(p)
    fC[tid] = cnt;
    fQ[tid] = ssq;
    __syncthreads();

    if (tid < 32) {
        double dA = 0.0, dC = 0.0, dQ = 0.0;
        #pragma unroll
        for (int j = 0; j < 8; ++j) {
            int k = tid + (j << 5);
            dA += (double)fA[k];
            dC += (double)fC[k];
            dQ += (double)fQ[k];
        }
        WARP_DRED(dA) WARP_DRED(dC) WARP_DRED(dQ)

        int fin = 0;
        int pb = patch * 43;
        if (tid == 0) {
            __stcg(&g_pA[pb + local], dA);
            __stcg(&g_pC[pb + local], dC);
            __stcg(&g_pQ[pb + local], dQ);
            __threadfence();
            int old = atomicAdd(&g_cnt[patch], 1);
            fin = (old == 42);
        }
        fin = __shfl_sync(0xffffffffu, fin, 0);

        if (fin) {                                 // finalize patch: argmin
            __threadfence();
            int lane = tid;
            double A[4], C[4], Q[4];
            double a = __ldcg(&g_pA[pb + lane]);          // scale0: 32 slices
            double c = __ldcg(&g_pC[pb + lane]);
            double q = __ldcg(&g_pQ[pb + lane]);
            WARP_DRED(a) WARP_DRED(c) WARP_DRED(q)
            A[0] = a; C[0] = c; Q[0] = q;
            a = (lane < 8) ? __ldcg(&g_pA[pb + 32 + lane]) : 0.0;   // scale1
            c = (lane < 8) ? __ldcg(&g_pC[pb + 32 + lane]) : 0.0;
            q = (lane < 8) ? __ldcg(&g_pQ[pb + 32 + lane]) : 0.0;
            WARP_DRED(a) WARP_DRED(c) WARP_DRED(q)
            A[1] = a; C[1] = c; Q[1] = q;
            a = (lane < 2) ? __ldcg(&g_pA[pb + 40 + lane]) : 0.0;   // scale2
            c = (lane < 2) ? __ldcg(&g_pC[pb + 40 + lane]) : 0.0;
            q = (lane < 2) ? __ldcg(&g_pQ[pb + 40 + lane]) : 0.0;
            WARP_DRED(a) WARP_DRED(c) WARP_DRED(q)
            A[2] = a; C[2] = c; Q[2] = q;
            A[3] = (lane == 0) ? __ldcg(&g_pA[pb + 42]) : 0.0;      // scale3
            C[3] = (lane == 0) ? __ldcg(&g_pC[pb + 42]) : 0.0;
            Q[3] = (lane == 0) ? __ldcg(&g_pQ[pb + 42]) : 0.0;

            if (lane == 0) {
                double best = 1e300;
                int mi = 0;
                #pragma unroll
                for (int i = 0; i < 4; ++i) {
                    double e = A[i] / (C[i] + (double)0.1f);
                    if (e < best) { best = e; mi = i; }   // first-min argmin
                }
                __stcg(&g_mask[patch], mi);
                __stcg(&g_Qsel[patch], Q[mi]);
                __threadfence();
                atomicAdd(&g_imgReady[patch >> 3], 1);
            }
        }
    }
    __syncthreads();
}

// ---------------------------------------------------------------------------
__device__ __forceinline__ void quad_val_s(
    int P0, const int* sm, int patchBase,
    const float* __restrict__ p0, const float* __restrict__ p1,
    const float* __restrict__ p2, const float* __restrict__ p3,
    const float* __restrict__ g0, const float* __restrict__ g1,
    const float* __restrict__ g2, const float* __restrict__ g3,
    float4& vo, float4& vl)
{
    int b  = P0 >> 20;
    int r  = P0 & 1048575;
    int Y  = r >> 10;
    int X  = r & 1023;
    int pr = Y >> 9;
    int pc = X >> 8;
    int mi = sm[((b << 3) | (pr << 2) | pc) - patchBase];
    int kh = 512 >> mi;
    int kw = 256 >> mi;
    int iy = (Y & 511) - ((512 - kh) >> 1);
    int ix = (X & 255) - ((256 - kw) >> 1);
    vo = make_float4(PADV, PADV, PADV, PADV);
    vl = vo;
    if ((unsigned)iy < (unsigned)kh && (unsigned)ix < (unsigned)kw) {
        int ws  = 10 - mi;
        int idx = (b << (2 * ws)) + ((pr * kh + iy) << ws)
                + (pc << (8 - mi)) + ix;
        const float* pp = (mi == 0) ? p0 : (mi == 1) ? p1 : (mi == 2) ? p2 : p3;
        const float* gg = (mi == 0) ? g0 : (mi == 1) ? g1 : (mi == 2) ? g2 : g3;
        float4 p = *(const float4*)(pp + idx);
        float4 q = *(const float4*)(gg + idx);
        vo = make_float4(p.x / 200.0f, p.y / 200.0f, p.z / 200.0f, p.w / 200.0f);
        vl = make_float4((q.x * 200.0f) / 200.0f, (q.y * 200.0f) / 200.0f,
                         (q.z * 200.0f) / 200.0f, (q.w * 200.0f) / 200.0f);
    }
}

__device__ __forceinline__ void pixel_val_s(
    int P, const int* sm, int patchBase,
    const float* __restrict__ p0, const float* __restrict__ p1,
    const float* __restrict__ p2, const float* __restrict__ p3,
    const float* __restrict__ g0, const float* __restrict__ g1,
    const float* __restrict__ g2, const float* __restrict__ g3,
    float& o, float& l)
{
    int b  = P >> 20;
    int r  = P & 1048575;
    int Y  = r >> 10;
    int X  = r & 1023;
    int pr = Y >> 9;
    int pc = X >> 8;
    int mi = sm[((b << 3) | (pr << 2) | pc) - patchBase];
    int kh = 512 >> mi;
    int kw = 256 >> mi;
    int iy = (Y & 511) - ((512 - kh) >> 1);
    int ix = (X & 255) - ((256 - kw) >> 1);
    o = PADV; l = PADV;
    if ((unsigned)iy < (unsigned)kh && (unsigned)ix < (unsigned)kw) {
        int ws  = 10 - mi;
        int idx = (b << (2 * ws)) + ((pr * kh + iy) << ws)
                + (pc << (8 - mi)) + ix;
        const float* pp = (mi == 0) ? p0 : (mi == 1) ? p1 : (mi == 2) ? p2 : p3;
        const float* gg = (mi == 0) ? g0 : (mi == 1) ? g1 : (mi == 2) ? g2 : g3;
        o = pp[idx] / 200.0f;
        l = (gg[idx] * 200.0f) / 200.0f;
    }
}

// ---------------------------------------------------------------------------
__global__ void __launch_bounds__(256)
k_fused(const float* __restrict__ p0, const float* __restrict__ p1,
        const float* __restrict__ p2, const float* __restrict__ p3,
        const float* __restrict__ g0, const float* __restrict__ g1,
        const float* __restrict__ g2, const float* __restrict__ g3,
        float* __restrict__ out)
{
    __shared__ float fA[256], fC[256], fQ[256];
    __shared__ int   s_tk;
    __shared__ int   s_mask[16];
    __shared__ float s_pub[8][6];

    int tid  = threadIdx.x;
    int w    = blockIdx.x;                        // 0..16383 (1024 px each)
    int base = w << 10;
    int b    = base >> 20;
    bool cross = ((w & 1023) == 1023) && (b < 15);

    // ---- help-first: reduce tasks ONLY until own image is ready ----
    while (true) {
        if (tid == 0) {
            bool ok = (atomicAdd(&g_imgReady[b], 0) == 8) &&
                      (!cross || atomicAdd(&g_imgReady[b + 1], 0) == 8);
            int tk = -1;                          // -1 => ready, go write
            if (!ok) {
                tk = atomicAdd(&g_ticket, 1);
                if (tk >= NTASK) { tk = -2; __nanosleep(256); }  // drained: nap
            }
            s_tk = tk;
        }
        __syncthreads();
        int tk = s_tk;
        __syncthreads();
        if (tk == -1) break;
        if (tk >= 0)
            reduce_task(tk, tid, p0, p1, p2, p3, g0, g1, g2, g3, fA, fC, fQ);
    }

    // ---- write chunk ----
    __threadfence();
    if (tid < 16) {
        int pidx = (b << 3) + tid;
        s_mask[tid] = (pidx < NPATCH) ? __ldcg(&g_mask[pidx]) : 0;
    }
    __syncthreads();

    int pb8  = b << 3;
    int g    = w * 256 + tid;                     // quad id
    int P0   = g << 2;
    int lane = tid & 31;
    int wrp  = tid >> 5;

    float4 vo, vl;
    quad_val_s(P0, s_mask, pb8, p0, p1, p2, p3, g0, g1, g2, g3, vo, vl);

    if (lane == 0) {
        s_pub[wrp][0] = vo.x; s_pub[wrp][1] = vo.y; s_pub[wrp][2] = vo.z;
        s_pub[wrp][3] = vl.x; s_pub[wrp][4] = vl.y; s_pub[wrp][5] = vl.z;
    }
    __syncthreads();

    float nox = __shfl_down_sync(0xffffffffu, vo.x, 1);
    float noy = __shfl_down_sync(0xffffffffu, vo.y, 1);
    float noz = __shfl_down_sync(0xffffffffu, vo.z, 1);
    float nlx = __shfl_down_sync(0xffffffffu, vl.x, 1);
    float nly = __shfl_down_sync(0xffffffffu, vl.y, 1);
    float nlz = __shfl_down_sync(0xffffffffu, vl.z, 1);

    bool lastGlobal = (g == 4194303);

    if (lane == 31) {
        if (tid != 255) {
            nox = s_pub[wrp + 1][0]; noy = s_pub[wrp + 1][1]; noz = s_pub[wrp + 1][2];
            nlx = s_pub[wrp + 1][3]; nly = s_pub[wrp + 1][4]; nlz = s_pub[wrp + 1][5];
        } else if (!lastGlobal) {
            int Pn = base + 1024;
            pixel_val_s(Pn,     s_mask, pb8, p0, p1, p2, p3, g0, g1, g2, g3, nox, nlx);
            pixel_val_s(Pn + 1, s_mask, pb8, p0, p1, p2, p3, g0, g1, g2, g3, noy, nly);
            pixel_val_s(Pn + 2, s_mask, pb8, p0, p1, p2, p3, g0, g1, g2, g3, noz, nlz);
        }
    }

    if (!lastGlobal) {
        float* ob = out + 1;
        float* lb = out + 1 + IMG0;
        int k = P0 + 3;                           // 16B aligned
        __stcs((float4*)(ob + k), make_float4(vo.w, nox, noy, noz));
        __stcs((float4*)(lb + k), make_float4(vl.w, nlx, nly, nlz));
    }
    // pixels 0,1,2 and 16777215 of both arrays handled in k_loss
}

// ---------------------------------------------------------------------------
__device__ __forceinline__ void pixel_val_g(
    int P,
    const float* __restrict__ p0, const float* __restrict__ p1,
    const float* __restrict__ p2, const float* __restrict__ p3,
    const float* __restrict__ g0, const float* __restrict__ g1,
    const float* __restrict__ g2, const float* __restrict__ g3,
    float& o, float& l)
{
    int b  = P >> 20;
    int r  = P & 1048575;
    int Y  = r >> 10;
    int X  = r & 1023;
    int pr = Y >> 9;
    int pc = X >> 8;
    int mi = g_mask[(b << 3) | (pr << 2) | pc];
    int kh = 512 >> mi;
    int kw = 256 >> mi;
    int iy = (Y & 511) - ((512 - kh) >> 1);
    int ix = (X & 255) - ((256 - kw) >> 1);
    o = PADV; l = PADV;
    if ((unsigned)iy < (unsigned)kh && (unsigned)ix < (unsigned)kw) {
        int ws  = 10 - mi;
        int idx = (b << (2 * ws)) + ((pr * kh + iy) << ws)
                + (pc << (8 - mi)) + ix;
        const float* pp = (mi == 0) ? p0 : (mi == 1) ? p1 : (mi == 2) ? p2 : p3;
        const float* gg = (mi == 0) ? g0 : (mi == 1) ? g1 : (mi == 2) ? g2 : g3;
        o = pp[idx] / 200.0f;
        l = (gg[idx] * 200.0f) / 200.0f;
    }
}

__global__ void k_loss(const float* __restrict__ p0, const float* __restrict__ p1,
                       const float* __restrict__ p2, const float* __restrict__ p3,
                       const float* __restrict__ g0, const float* __restrict__ g1,
                       const float* __restrict__ g2, const float* __restrict__ g3,
                       float* __restrict__ out)
{
    int t = threadIdx.x;
    if (t == 0) {
        double num[4] = {0.0, 0.0, 0.0, 0.0};
        int    cnt[4] = {0, 0, 0, 0};
        for (int p = 0; p < NPATCH; ++p) {        // fixed order: deterministic
            int mi = g_mask[p];
            num[mi] += g_Qsel[p];
            cnt[mi] += 1;
        }
        const double w[4]  = {0.5, 0.25, 0.125, 0.0625};
        const double pe[4] = {131072.0, 32768.0, 8192.0, 2048.0};
        double loss = 0.0;
        #pragma unroll
        for (int i = 0; i < 4; ++i)
            loss += w[i] * (num[i] / ((double)cnt[i] * pe[i] + (double)0.01f));
        out[0] = (float)loss;
    } else if (t < 5) {
        const int Ps[4] = {0, 1, 2, 16777215};
        int P = Ps[t - 1];
        float o, l;
        pixel_val_g(P, p0, p1, p2, p3, g0, g1, g2, g3, o, l);
        out[1 + P] = o;
        out[1 + IMG0 + P] = l;
    }
}

// ---------------------------------------------------------------------------
extern "C" void kernel_launch(void* const* d_in, const int* in_sizes, int n_in,
                              void* d_out, int out_size)
{
    const float *pre[4], *gt[4];
    if (n_in >= 8 && in_sizes[1] == in_sizes[0]) {        // interleaved
        for (int i = 0; i < 4; ++i) {
            pre[i] = (const float*)d_in[2 * i];
            gt [i] = (const float*)d_in[2 * i + 1];
        }
    } else {                                              // grouped
        for (int i = 0; i < 4; ++i) {
            pre[i] = (const float*)d_in[i];
            gt [i] = (const float*)d_in[4 + i];
        }
    }
    float* out = (float*)d_out;

    k_zero<<<1, 160>>>();
    k_fused<<<16384, 256>>>(pre[0], pre[1], pre[2], pre[3],
                            gt[0], gt[1], gt[2], gt[3], out);
    k_loss<<<1, 32>>>(pre[0], pre[1], pre[2], pre[3],
                      gt[0], gt[1], gt[2], gt[3], out);
    (void)out_size;
}

// round 10
// speedup vs baseline: 1.2435x; 1.2400x over previous
#include <cuda_runtime.h>

// ---------------------------------------------------------------------------
// B=16, H=W=1024, ROUTE=(512,256) -> ph=2, pw=4, L=8, NPATCH=128
// out: [0]=loss, [1..16M]=out_img, [16M+1..32M]=lab_img
//
// Static-role fused kernel: blocks [0,5504) each run ONE reduce task
// (image-major; identical shape to the proven standalone reduce), blocks
// [5504,21888) are writers that spin on a per-image ready flag then run the
// proven R4 write path. Read & write DRAM streams overlap; deadlock-free by
// dispatch order (all reduce bids precede all writer bids).
// ---------------------------------------------------------------------------

#define NPATCH 128
#define IMG0   16777216
#define NTASK  5504           // 16 images x 8 patches x 43 slices
#define NWBLK  16384
#define PADV   (0.2f / 200.0f)

__device__ double g_pA[NPATCH * 43];
__device__ double g_pC[NPATCH * 43];
__device__ double g_pQ[NPATCH * 43];
__device__ double g_Qsel[NPATCH];
__device__ int    g_mask[NPATCH];
__device__ int    g_cnt[NPATCH];
__device__ int    g_imgReady[16];

// ---------------------------------------------------------------------------
__global__ void k_zero() {
    int t = threadIdx.x;
    if (t < NPATCH) g_cnt[t] = 0;
    if (t < 16)     g_imgReady[t] = 0;
}

// ---------------------------------------------------------------------------
#define WARP_DRED(v) { v += __shfl_down_sync(0xffffffffu, v, 16); \
                       v += __shfl_down_sync(0xffffffffu, v, 8);  \
                       v += __shfl_down_sync(0xffffffffu, v, 4);  \
                       v += __shfl_down_sync(0xffffffffu, v, 2);  \
                       v += __shfl_down_sync(0xffffffffu, v, 1); }

// ---------------------------------------------------------------------------
// Single-pixel compose value (uses global g_mask; only called post-ready).
__device__ __forceinline__ void pixel_val(
    int P,
    const float* __restrict__ p0, const float* __restrict__ p1,
    const float* __restrict__ p2, const float* __restrict__ p3,
    const float* __restrict__ g0, const float* __restrict__ g1,
    const float* __restrict__ g2, const float* __restrict__ g3,
    float& o, float& l)
{
    int b  = P >> 20;
    int r  = P & 1048575;
    int Y  = r >> 10;
    int X  = r & 1023;
    int pr = Y >> 9;
    int pc = X >> 8;
    int mi = g_mask[(b << 3) | (pr << 2) | pc];
    int kh = 512 >> mi;
    int kw = 256 >> mi;
    int iy = (Y & 511) - ((512 - kh) >> 1);
    int ix = (X & 255) - ((256 - kw) >> 1);
    o = PADV; l = PADV;
    if ((unsigned)iy < (unsigned)kh && (unsigned)ix < (unsigned)kw) {
        int ws  = 10 - mi;
        int idx = (b << (2 * ws)) + ((pr * kh + iy) << ws)
                + (pc << (8 - mi)) + ix;
        const float* pp = (mi == 0) ? p0 : (mi == 1) ? p1 : (mi == 2) ? p2 : p3;
        const float* gg = (mi == 0) ? g0 : (mi == 1) ? g1 : (mi == 2) ? g2 : g3;
        o = pp[idx] / 200.0f;
        l = (gg[idx] * 200.0f) / 200.0f;
    }
}

// ---------------------------------------------------------------------------
__global__ void __launch_bounds__(256)
k_main(const float* __restrict__ p0, const float* __restrict__ p1,
       const float* __restrict__ p2, const float* __restrict__ p3,
       const float* __restrict__ g0, const float* __restrict__ g1,
       const float* __restrict__ g2, const float* __restrict__ g3,
       float* __restrict__ out)
{
    int bid = blockIdx.x;
    int tid = threadIdx.x;

    if (bid < NTASK) {
        // ================= REDUCE ROLE (one task, then exit) ==============
        // tk = img*344 + patch_local*43 + s; s:[0,32)=s0 [32,40)=s1 [40,42)=s2 42=s3
        int tk  = bid;
        int img = tk / 344;
        int r   = tk - img * 344;
        int pl  = r / 43;
        int s   = r - pl * 43;
        int patch = (img << 3) + pl;

        int scale, slice;
        if      (s < 32) { scale = 0; slice = s;      }
        else if (s < 40) { scale = 1; slice = s - 32; }
        else if (s < 42) { scale = 2; slice = s - 40; }
        else             { scale = 3; slice = 0;      }

        const int kwS_t[4] = {8, 7, 6, 5};
        const int wS_t[4]  = {10, 9, 8, 7};
        int kwS = kwS_t[scale];
        int wS  = wS_t[scale];

        const float* pre = (scale == 0) ? p0 : (scale == 1) ? p1 : (scale == 2) ? p2 : p3;
        const float* gt  = (scale == 0) ? g0 : (scale == 1) ? g1 : (scale == 2) ? g2 : g3;

        int b  = patch >> 3;
        int pr = (patch >> 2) & 1;
        int pc = patch & 3;

        int qpwS = kwS - 2;
        int row  = tid >> qpwS;
        int col4 = (tid & ((1 << qpwS) - 1)) << 2;
        int rpi  = 256 >> qpwS;
        int rpb  = (scale == 3) ? (rpi << 1) : (rpi << 2);

        int kh  = 512 >> scale;
        int gy  = pr * kh + slice * rpb + row;
        int gx  = (pc << kwS) + col4;
        int idx = (b << (2 * wS)) + (gy << wS) + gx;

        float4 P[4], G[4];
        int nit;
        if (scale == 0) {                          // caching: L2-resident for writers
            P[0] = *(const float4*)(pre + idx);
            G[0] = *(const float4*)(gt  + idx);
            P[1] = *(const float4*)(pre + idx + 4096);
            G[1] = *(const float4*)(gt  + idx + 4096);
            P[2] = *(const float4*)(pre + idx + 8192);
            G[2] = *(const float4*)(gt  + idx + 8192);
            P[3] = *(const float4*)(pre + idx + 12288);
            G[3] = *(const float4*)(gt  + idx + 12288);
            nit = 4;
        } else if (scale != 3) {
            P[0] = __ldcs((const float4*)(pre + idx));
            G[0] = __ldcs((const float4*)(gt  + idx));
            P[1] = __ldcs((const float4*)(pre + idx + 4096));
            G[1] = __ldcs((const float4*)(gt  + idx + 4096));
            P[2] = __ldcs((const float4*)(pre + idx + 8192));
            G[2] = __ldcs((const float4*)(gt  + idx + 8192));
            P[3] = __ldcs((const float4*)(pre + idx + 12288));
            G[3] = __ldcs((const float4*)(gt  + idx + 12288));
            nit = 4;
        } else {
            P[0] = __ldcs((const float4*)(pre + idx));
            G[0] = __ldcs((const float4*)(gt  + idx));
            P[1] = __ldcs((const float4*)(pre + idx + 4096));
            G[1] = __ldcs((const float4*)(gt  + idx + 4096));
            nit = 2;
        }

        float sg = 0.f, spp = 0.f, cnt = 0.f, ssq = 0.f;
        #define ACC(pp, gg) { float e = fmaf((gg), -200.0f, (pp));       \
                              ssq = fmaf(e, e, ssq); sg += (gg);         \
                              if (e < 0.0f) { cnt += 1.0f; spp += (pp); } }
        #pragma unroll
        for (int it = 0; it < 4; ++it) {
            if (it < nit) {
                ACC(P[it].x, G[it].x) ACC(P[it].y, G[it].y)
                ACC(P[it].z, G[it].z) ACC(P[it].w, G[it].w)
            }
        }
        #undef ACC

        __shared__ float fA[256], fC[256], fQ[256];
        fA[tid] = fmaf(sg, 200.0f, -spp);          // sabs = 200*Sum(g)-Sum_pos(p)
        fC[tid] = cnt;
        fQ[tid] = ssq;
        __syncthreads();

        if (tid < 32) {
            double dA = 0.0, dC = 0.0, dQ = 0.0;
            #pragma unroll
            for (int j = 0; j < 8; ++j) {
                int k = tid + (j << 5);
                dA += (double)fA[k];
                dC += (double)fC[k];
                dQ += (double)fQ[k];
            }
            WARP_DRED(dA) WARP_DRED(dC) WARP_DRED(dQ)

            int fin = 0;
            int pb = patch * 43;
            if (tid == 0) {
                __stcg(&g_pA[pb + s], dA);
                __stcg(&g_pC[pb + s], dC);
                __stcg(&g_pQ[pb + s], dQ);
                __threadfence();
                int old = atomicAdd(&g_cnt[patch], 1);
                fin = (old == 42);
            }
            fin = __shfl_sync(0xffffffffu, fin, 0);

            if (fin) {                             // finalize patch: argmin
                __threadfence();
                int lane = tid;
                double A[4], C[4], Q[4];
                double a = __ldcg(&g_pA[pb + lane]);        // scale0: 32
                double c = __ldcg(&g_pC[pb + lane]);
                double q = __ldcg(&g_pQ[pb + lane]);
                WARP_DRED(a) WARP_DRED(c) WARP_DRED(q)
                A[0] = a; C[0] = c; Q[0] = q;
                a = (lane < 8) ? __ldcg(&g_pA[pb + 32 + lane]) : 0.0;   // scale1
                c = (lane < 8) ? __ldcg(&g_pC[pb + 32 + lane]) : 0.0;
                q = (lane < 8) ? __ldcg(&g_pQ[pb + 32 + lane]) : 0.0;
                WARP_DRED(a) WARP_DRED(c) WARP_DRED(q)
                A[1] = a; C[1] = c; Q[1] = q;
                a = (lane < 2) ? __ldcg(&g_pA[pb + 40 + lane]) : 0.0;   // scale2
                c = (lane < 2) ? __ldcg(&g_pC[pb + 40 + lane]) : 0.0;
                q = (lane < 2) ? __ldcg(&g_pQ[pb + 40 + lane]) : 0.0;
                WARP_DRED(a) WARP_DRED(c) WARP_DRED(q)
                A[2] = a; C[2] = c; Q[2] = q;
                A[3] = (lane == 0) ? __ldcg(&g_pA[pb + 42]) : 0.0;      // scale3
                C[3] = (lane == 0) ? __ldcg(&g_pC[pb + 42]) : 0.0;
                Q[3] = (lane == 0) ? __ldcg(&g_pQ[pb + 42]) : 0.0;

                if (lane == 0) {
                    double best = 1e300;
                    int mi = 0;
                    #pragma unroll
                    for (int i = 0; i < 4; ++i) {
                        double e = A[i] / (C[i] + (double)0.1f);
                        if (e < best) { best = e; mi = i; }  // first-min argmin
                    }
                    __stcg(&g_mask[patch], mi);
                    __stcg(&g_Qsel[patch], Q[mi]);
                    __threadfence();
                    atomicAdd(&g_imgReady[patch >> 3], 1);
                }
            }
        }
        return;
    }

    // ==================== WRITER ROLE (R4 scheme) =========================
    int q = (bid - NTASK) * 256 + tid;            // quad id, 0..4194303
    int P0 = (q << 2) + 3;
    int b  = P0 >> 20;
    bool crossB = (b < 15) && (((P0 & 1048575) >> 10) == 1023) &&
                  ((P0 & 1023) >= 1020);          // quad reaching into image b+1

    if (tid == 0) {
        int spin = 32;
        while (atomicAdd(&g_imgReady[b], 0) < 8) { __nanosleep(spin); if (spin < 4096) spin <<= 1; }
    }
    __syncthreads();
    if (crossB) {                                 // rare: last quad of an image
        int spin = 32;
        while (atomicAdd(&g_imgReady[b + 1], 0) < 8) { __nanosleep(spin); if (spin < 4096) spin <<= 1; }
    }
    __threadfence();

    float* ob = out + 1;
    float* lb = out + 1 + IMG0;

    if (q == 4194303) {                           // edge pixels
        int Ps[4] = {0, 1, 2, 16777215};
        #pragma unroll
        for (int i = 0; i < 4; ++i) {
            float o, l;
            pixel_val(Ps[i], p0, p1, p2, p3, g0, g1, g2, g3, o, l);
            ob[Ps[i]] = o;
            lb[Ps[i]] = l;
        }
        return;
    }

    int r  = P0 & 1048575;
    int Y  = r >> 10;
    int X0 = r & 1023;

    float4 vo = make_float4(PADV, PADV, PADV, PADV);
    float4 vl = vo;

    if ((X0 & 255) != 255) {
        // same row, same patch for all 4 pixels
        int pr = Y >> 9;
        int pc = X0 >> 8;
        int mi = g_mask[(b << 3) | (pr << 2) | pc];
        int kh = 512 >> mi;
        int kw = 256 >> mi;
        int iy = (Y & 511) - ((512 - kh) >> 1);
        int ix = (X0 & 255) - ((256 - kw) >> 1);
        bool yin = (unsigned)iy < (unsigned)kh;

        if (yin && ix >= 0 && ix + 3 < kw) {
            int ws  = 10 - mi;
            int idx = (b << (2 * ws)) + ((pr * kh + iy) << ws)
                    + (pc << (8 - mi)) + ix;
            const float* pp = (mi == 0) ? p0 : (mi == 1) ? p1 : (mi == 2) ? p2 : p3;
            const float* gg = (mi == 0) ? g0 : (mi == 1) ? g1 : (mi == 2) ? g2 : g3;
            vo = make_float4(pp[idx] / 200.0f, pp[idx + 1] / 200.0f,
                             pp[idx + 2] / 200.0f, pp[idx + 3] / 200.0f);
            vl = make_float4((gg[idx]     * 200.0f) / 200.0f,
                             (gg[idx + 1] * 200.0f) / 200.0f,
                             (gg[idx + 2] * 200.0f) / 200.0f,
                             (gg[idx + 3] * 200.0f) / 200.0f);
        } else if (yin && ix + 3 >= 0 && ix < kw) {
            // x-straddle: per-pixel inside test
            int ws  = 10 - mi;
            const float* pp = (mi == 0) ? p0 : (mi == 1) ? p1 : (mi == 2) ? p2 : p3;
            const float* gg = (mi == 0) ? g0 : (mi == 1) ? g1 : (mi == 2) ? g2 : g3;
            float o[4], l[4];
            #pragma unroll
            for (int j = 0; j < 4; ++j) {
                int ixj = ix + j;
                o[j] = PADV; l[j] = PADV;
                if ((unsigned)ixj < (unsigned)kw) {
                    int idx = (b << (2 * ws)) + ((pr * kh + iy) << ws)
                            + (pc << (8 - mi)) + ixj;
                    o[j] = pp[idx] / 200.0f;
                    l[j] = (gg[idx] * 200.0f) / 200.0f;
                }
            }
            vo = make_float4(o[0], o[1], o[2], o[3]);
            vl = make_float4(l[0], l[1], l[2], l[3]);
        }
        // else: fully outside -> PADV
    } else {
        // crosses patch column (and possibly row/batch): full per-pixel
        float o[4], l[4];
        #pragma unroll
        for (int j = 0; j < 4; ++j)
            pixel_val(P0 + j, p0, p1, p2, p3, g0, g1, g2, g3, o[j], l[j]);
        vo = make_float4(o[0], o[1], o[2], o[3]);
        vl = make_float4(l[0], l[1], l[2], l[3]);
    }

    __stcs((float4*)(ob + P0), vo);
    __stcs((float4*)(lb + P0), vl);
}

// ---------------------------------------------------------------------------
__global__ void k_loss(float* __restrict__ out)
{
    if (threadIdx.x == 0) {
        double num[4] = {0.0, 0.0, 0.0, 0.0};
        int    cnt[4] = {0, 0, 0, 0};
        for (int p = 0; p < NPATCH; ++p) {        // fixed order: deterministic
            int mi = g_mask[p];
            num[mi] += g_Qsel[p];
            cnt[mi] += 1;
        }
        const double w[4]  = {0.5, 0.25, 0.125, 0.0625};
        const double pe[4] = {131072.0, 32768.0, 8192.0, 2048.0};
        double loss = 0.0;
        #pragma unroll
        for (int i = 0; i < 4; ++i)
            loss += w[i] * (num[i] / ((double)cnt[i] * pe[i] + (double)0.01f));
        out[0] = (float)loss;
    }
}

// ---------------------------------------------------------------------------
extern "C" void kernel_launch(void* const* d_in, const int* in_sizes, int n_in,
                              void* d_out, int out_size)
{
    const float *pre[4], *gt[4];
    if (n_in >= 8 && in_sizes[1] == in_sizes[0]) {        // interleaved
        for (int i = 0; i < 4; ++i) {
            pre[i] = (const float*)d_in[2 * i];
            gt [i] = (const float*)d_in[2 * i + 1];
        }
    } else {                                              // grouped
        for (int i = 0; i < 4; ++i) {
            pre[i] = (const float*)d_in[i];
            gt [i] = (const float*)d_in[4 + i];
        }
    }
    float* out = (float*)d_out;

    k_zero<<<1, 160>>>();
    k_main<<<NTASK + NWBLK, 256>>>(pre[0], pre[1], pre[2], pre[3],
                                   gt[0], gt[1], gt[2], gt[3], out);
    k_loss<<<1, 32>>>(out);
    (void)out_size;
}

// round 12
// speedup vs baseline: 1.6032x; 1.2893x over previous
#include <cuda_runtime.h>

// ---------------------------------------------------------------------------
// B=16, H=W=1024, ROUTE=(512,256) -> ph=2, pw=4, L=8, NPATCH=128
// scale i: W_i=1024>>i, kh=512>>i, kw=256>>i
// out: [0]=loss, [1..16M]=out_img, [16M+1..32M]=lab_img
//
// Best-of-each-phase assembly:
//   k_reduce: R6 (transposed slots, ldcs ordering, lb(256,6))   ~34.1 us
//   k_select: R6 (coalesced transposed scan)                    ~1.5 us
//   k_write : R4 (scalar-gather fast path, aligned STG.128 stcs) ~47 us
// ---------------------------------------------------------------------------

#define NPATCH 128
#define IMG0   16777216
#define NSLOTS 5504   // transposed slots: base + slice*128 + patch
#define PADV   (0.2f / 200.0f)

__device__ double g_pA[NSLOTS];
__device__ double g_pC[NSLOTS];
__device__ double g_pQ[NSLOTS];
__device__ int    g_mask[NPATCH];

// ---------------------------------------------------------------------------
// Fused per-patch reduction. Scales 1-3 first (streaming loads), scale 0
// (128 MB ~= L2) last with caching loads so k_write's gathers can hit L2.
// Partial sums stored TRANSPOSED (slice-major) for coalesced k_select reads.
__global__ void __launch_bounds__(256, 6)
k_reduce(const float* __restrict__ p0, const float* __restrict__ p1,
         const float* __restrict__ p2, const float* __restrict__ p3,
         const float* __restrict__ g0, const float* __restrict__ g1,
         const float* __restrict__ g2, const float* __restrict__ g3)
{
    int bid = blockIdx.x;
    int scale, rel, sbase;
    if      (bid < 1024) { scale = 1; rel = bid;        sbase = 0;    }
    else if (bid < 1280) { scale = 2; rel = bid - 1024; sbase = 1024; }
    else if (bid < 1408) { scale = 3; rel = bid - 1280; sbase = 1280; }
    else                 { scale = 0; rel = bid - 1408; sbase = 1408; }

    const int kwS_t[4]  = {8, 7, 6, 5};
    const int wS_t[4]   = {10, 9, 8, 7};
    const int bppS_t[4] = {5, 3, 1, 0};

    int kwS  = kwS_t[scale];
    int wS   = wS_t[scale];
    int bppS = bppS_t[scale];

    const float* pre = (scale == 0) ? p0 : (scale == 1) ? p1 : (scale == 2) ? p2 : p3;
    const float* gt  = (scale == 0) ? g0 : (scale == 1) ? g1 : (scale == 2) ? g2 : g3;

    int patch = rel >> bppS;
    int slice = rel & ((1 << bppS) - 1);
    int b  = patch >> 3;
    int pr = (patch >> 2) & 1;
    int pc = patch & 3;

    int qpwS = kwS - 2;
    int row  = threadIdx.x >> qpwS;
    int col4 = (threadIdx.x & ((1 << qpwS) - 1)) << 2;
    int rpi  = 256 >> qpwS;
    int rpb  = rpi << 2;
    if (scale == 3) rpb = rpi << 1;

    int kh  = 512 >> scale;
    int gy  = pr * kh + slice * rpb + row;
    int gx  = (pc << kwS) + col4;
    int idx = (b << (2 * wS)) + (gy << wS) + gx;

    float4 P[4], G[4];
    int nit;
    if (scale == 0) {
        P[0] = *(const float4*)(pre + idx);
        G[0] = *(const float4*)(gt  + idx);
        P[1] = *(const float4*)(pre + idx + 4096);
        G[1] = *(const float4*)(gt  + idx + 4096);
        P[2] = *(const float4*)(pre + idx + 8192);
        G[2] = *(const float4*)(gt  + idx + 8192);
        P[3] = *(const float4*)(pre + idx + 12288);
        G[3] = *(const float4*)(gt  + idx + 12288);
        nit = 4;
    } else if (scale != 3) {
        P[0] = __ldcs((const float4*)(pre + idx));
        G[0] = __ldcs((const float4*)(gt  + idx));
        P[1] = __ldcs((const float4*)(pre + idx + 4096));
        G[1] = __ldcs((const float4*)(gt  + idx + 4096));
        P[2] = __ldcs((const float4*)(pre + idx + 8192));
        G[2] = __ldcs((const float4*)(gt  + idx + 8192));
        P[3] = __ldcs((const float4*)(pre + idx + 12288));
        G[3] = __ldcs((const float4*)(gt  + idx + 12288));
        nit = 4;
    } else {
        P[0] = __ldcs((const float4*)(pre + idx));
        G[0] = __ldcs((const float4*)(gt  + idx));
        P[1] = __ldcs((const float4*)(pre + idx + 4096));
        G[1] = __ldcs((const float4*)(gt  + idx + 4096));
        nit = 2;
    }

    float sg = 0.f, spp = 0.f, cnt = 0.f, ssq = 0.f;

    #define ACC(pp, gg) { float e = fmaf((gg), -200.0f, (pp));       \
                          ssq = fmaf(e, e, ssq); sg += (gg);         \
                          if (e < 0.0f) { cnt += 1.0f; spp += (pp); } }
    #pragma unroll
    for (int it = 0; it < 4; ++it) {
        if (it < nit) {
            ACC(P[it].x, G[it].x) ACC(P[it].y, G[it].y)
            ACC(P[it].z, G[it].z) ACC(P[it].w, G[it].w)
        }
    }
    #undef ACC

    __shared__ float fA[256], fC[256], fQ[256];
    int tid = threadIdx.x;
    fA[tid] = fmaf(sg, 200.0f, -spp);          // sabs = 200*Sum(g) - Sum_pos(p)
    fC[tid] = cnt;
    fQ[tid] = ssq;
    __syncthreads();

    if (tid < 32) {
        double dA = 0.0, dC = 0.0, dQ = 0.0;
        #pragma unroll
        for (int j = 0; j < 8; ++j) {
            int k = tid + (j << 5);
            dA += (double)fA[k];
            dC += (double)fC[k];
            dQ += (double)fQ[k];
        }
        #pragma unroll
        for (int off = 16; off > 0; off >>= 1) {
            dA += __shfl_down_sync(0xffffffffu, dA, off);
            dC += __shfl_down_sync(0xffffffffu, dC, off);
            dQ += __shfl_down_sync(0xffffffffu, dQ, off);
        }
        if (tid == 0) {
            int slot = sbase + slice * NPATCH + patch;   // transposed
            g_pA[slot] = dA;
            g_pC[slot] = dC;
            g_pQ[slot] = dQ;
        }
    }
}

// ---------------------------------------------------------------------------
// Per-patch argmin + weighted loss. 1 block, 128 threads; slice-major slots
// make each scan iteration a coalesced 1KB read.
__global__ void k_select(float* __restrict__ out)
{
    int t = threadIdx.x;
    __shared__ double num[4];
    __shared__ int    cnt[4];
    if (t < 4) { num[t] = 0.0; cnt[t] = 0; }
    __syncthreads();

    const int base4[4] = {1408, 0, 1024, 1280};
    const int cnt4[4]  = {32, 8, 2, 1};

    double best = 1e300;
    int mi = 0;
    double ssqs[4];
    #pragma unroll
    for (int i = 0; i < 4; ++i) {
        double A = 0.0, C = 0.0, Q = 0.0;
        #pragma unroll 8
        for (int s = 0; s < cnt4[i]; ++s) {
            int slot = base4[i] + s * NPATCH + t;
            A += g_pA[slot];
            C += g_pC[slot];
            Q += g_pQ[slot];
        }
        ssqs[i] = Q;
        double e = A / (C + (double)0.1f);
        if (e < best) { best = e; mi = i; }   // strict < = first-min (argmin)
    }
    g_mask[t] = mi;
    atomicAdd(&num[mi], ssqs[mi]);
    atomicAdd(&cnt[mi], 1);
    __syncthreads();

    if (t == 0) {
        const double w[4]  = {0.5, 0.25, 0.125, 0.0625};
        const double pe[4] = {131072.0, 32768.0, 8192.0, 2048.0};
        double loss = 0.0;
        #pragma unroll
        for (int i = 0; i < 4; ++i)
            loss += w[i] * (num[i] / ((double)cnt[i] * pe[i] + (double)0.01f));
        out[0] = (float)loss;
    }
}

// ---------------------------------------------------------------------------
// Single-pixel compose value (slow path / edges).
__device__ __forceinline__ void pixel_val(
    int P,
    const float* __restrict__ p0, const float* __restrict__ p1,
    const float* __restrict__ p2, const float* __restrict__ p3,
    const float* __restrict__ g0, const float* __restrict__ g1,
    const float* __restrict__ g2, const float* __restrict__ g3,
    float& o, float& l)
{
    int b  = P >> 20;
    int r  = P & 1048575;
    int Y  = r >> 10;
    int X  = r & 1023;
    int pr = Y >> 9;
    int pc = X >> 8;
    int mi = g_mask[(b << 3) | (pr << 2) | pc];
    int kh = 512 >> mi;
    int kw = 256 >> mi;
    int iy = (Y & 511) - ((512 - kh) >> 1);
    int ix = (X & 255) - ((256 - kw) >> 1);
    o = PADV; l = PADV;
    if ((unsigned)iy < (unsigned)kh && (unsigned)ix < (unsigned)kw) {
        int ws  = 10 - mi;
        int idx = (b << (2 * ws)) + ((pr * kh + iy) << ws)
                + (pc << (8 - mi)) + ix;
        const float* pp = (mi == 0) ? p0 : (mi == 1) ? p1 : (mi == 2) ? p2 : p3;
        const float* gg = (mi == 0) ? g0 : (mi == 1) ? g1 : (mi == 2) ? g2 : g3;
        o = pp[idx] / 200.0f;
        l = (gg[idx] * 200.0f) / 200.0f;
    }
}

// ---------------------------------------------------------------------------
// Compose out_img & lab_img (R4 scheme, best measured). Thread q computes
// pixels P=4q+3..4q+6 so the output quad (out+1+P) is 16B-aligned -> direct
// STG.128 from registers via __stcs. Fast path = all 4 pixels in the same
// row & patch column (63/64 of quads). Edge pixels handled by last thread.
__global__ void __launch_bounds__(256)
k_write(const float* __restrict__ p0, const float* __restrict__ p1,
        const float* __restrict__ p2, const float* __restrict__ p3,
        const float* __restrict__ g0, const float* __restrict__ g1,
        const float* __restrict__ g2, const float* __restrict__ g3,
        float* __restrict__ out)
{
    int q = blockIdx.x * 256 + threadIdx.x;      // 0..4194303
    float* ob = out + 1;
    float* lb = out + 1 + IMG0;

    if (q == 4194303) {                          // edge pixels
        int Ps[4] = {0, 1, 2, 16777215};
        #pragma unroll
        for (int i = 0; i < 4; ++i) {
            float o, l;
            pixel_val(Ps[i], p0, p1, p2, p3, g0, g1, g2, g3, o, l);
            ob[Ps[i]] = o;
            lb[Ps[i]] = l;
        }
        return;
    }

    int P0 = (q << 2) + 3;
    int b  = P0 >> 20;
    int r  = P0 & 1048575;
    int Y  = r >> 10;
    int X0 = r & 1023;

    float4 vo = make_float4(PADV, PADV, PADV, PADV);
    float4 vl = vo;

    if ((X0 & 255) != 255) {
        // same row, same patch for all 4 pixels
        int pr = Y >> 9;
        int pc = X0 >> 8;
        int mi = g_mask[(b << 3) | (pr << 2) | pc];
        int kh = 512 >> mi;
        int kw = 256 >> mi;
        int iy = (Y & 511) - ((512 - kh) >> 1);
        int ix = (X0 & 255) - ((256 - kw) >> 1);
        bool yin = (unsigned)iy < (unsigned)kh;

        if (yin && ix >= 0 && ix + 3 < kw) {
            int ws  = 10 - mi;
            int idx = (b << (2 * ws)) + ((pr * kh + iy) << ws)
                    + (pc << (8 - mi)) + ix;
            const float* pp = (mi == 0) ? p0 : (mi == 1) ? p1 : (mi == 2) ? p2 : p3;
            const float* gg = (mi == 0) ? g0 : (mi == 1) ? g1 : (mi == 2) ? g2 : g3;
            vo = make_float4(pp[idx] / 200.0f, pp[idx + 1] / 200.0f,
                             pp[idx + 2] / 200.0f, pp[idx + 3] / 200.0f);
            vl = make_float4((gg[idx]     * 200.0f) / 200.0f,
                             (gg[idx + 1] * 200.0f) / 200.0f,
                             (gg[idx + 2] * 200.0f) / 200.0f,
                             (gg[idx + 3] * 200.0f) / 200.0f);
        } else if (yin && ix + 3 >= 0 && ix < kw) {
            // x-straddle (ix==-1 or ix==kw-1): per-pixel inside test
            int ws  = 10 - mi;
            const float* pp = (mi == 0) ? p0 : (mi == 1) ? p1 : (mi == 2) ? p2 : p3;
            const float* gg = (mi == 0) ? g0 : (mi == 1) ? g1 : (mi == 2) ? g2 : g3;
            float o[4], l[4];
            #pragma unroll
            for (int j = 0; j < 4; ++j) {
                int ixj = ix + j;
                o[j] = PADV; l[j] = PADV;
                if ((unsigned)ixj < (unsigned)kw) {
                    int idx = (b << (2 * ws)) + ((pr * kh + iy) << ws)
                            + (pc << (8 - mi)) + ixj;
                    o[j] = pp[idx] / 200.0f;
                    l[j] = (gg[idx] * 200.0f) / 200.0f;
                }
            }
            vo = make_float4(o[0], o[1], o[2], o[3]);
            vl = make_float4(l[0], l[1], l[2], l[3]);
        }
        // else: fully outside -> PADV (already set)
    } else {
        // crosses patch column (and possibly row/batch): full per-pixel
        float o[4], l[4];
        #pragma unroll
        for (int j = 0; j < 4; ++j)
            pixel_val(P0 + j, p0, p1, p2, p3, g0, g1, g2, g3, o[j], l[j]);
        vo = make_float4(o[0], o[1], o[2], o[3]);
        vl = make_float4(l[0], l[1], l[2], l[3]);
    }

    __stcs((float4*)(ob + P0), vo);
    __stcs((float4*)(lb + P0), vl);
}

// ---------------------------------------------------------------------------
extern "C" void kernel_launch(void* const* d_in, const int* in_sizes, int n_in,
                              void* d_out, int out_size)
{
    const float *pre[4], *gt[4];
    if (n_in >= 8 && in_sizes[1] == in_sizes[0]) {        // interleaved
        for (int i = 0; i < 4; ++i) {
            pre[i] = (const float*)d_in[2 * i];
            gt [i] = (const float*)d_in[2 * i + 1];
        }
    } else {                                              // grouped
        for (int i = 0; i < 4; ++i) {
            pre[i] = (const float*)d_in[i];
            gt [i] = (const float*)d_in[4 + i];
        }
    }
    float* out = (float*)d_out;

    k_reduce<<<NSLOTS, 256>>>(pre[0], pre[1], pre[2], pre[3],
                              gt[0], gt[1], gt[2], gt[3]);
    k_select<<<1, 128>>>(out);
    k_write<<<16384, 256>>>(pre[0], pre[1], pre[2], pre[3],
                            gt[0], gt[1], gt[2], gt[3], out);
    (void)out_size;
}